// round 1
// baseline (speedup 1.0000x reference)
#include <cuda_runtime.h>
#include <cuda_fp16.h>

// LSTM Autoencoder: B=512, T=256, D=H=128, gates G=4H=512.
// Persistent kernel: 128 CTAs x 512 threads; each CTA owns 4 batch rows and the
// full recurrence (encoder 2 layers -> decoder 2 layers + output projection).
// Batch rows are independent => no cross-CTA sync.
// Weights pre-packed by prep_kernel into k-major __half2 (Wih,Whh) pairs to
// halve L2 traffic; all state/accumulation in fp32.

#define Bsz 512
#define Tt  256
#define Dd  128
#define Hh  128
#define Gg  512

// __device__ scratch (allocation-free rule): packed weights + fused biases.
__device__ __align__(16) __half2 g_E0[128 * 512];
__device__ __align__(16) __half2 g_E1[128 * 512];
__device__ __align__(16) __half2 g_D0[128 * 512];
__device__ __align__(16) __half2 g_D1[128 * 512];
__device__ __align__(16) float   g_OW[128 * 128];   // out_W transposed: [k][d]
__device__ float g_bE0[512], g_bE1[512], g_bD0[512], g_bD1[512];

__global__ void prep_kernel(
    const float* __restrict__ eW0, const float* __restrict__ eU0,
    const float* __restrict__ ebi0, const float* __restrict__ ebh0,
    const float* __restrict__ eW1, const float* __restrict__ eU1,
    const float* __restrict__ ebi1, const float* __restrict__ ebh1,
    const float* __restrict__ dW0, const float* __restrict__ dU0,
    const float* __restrict__ dbi0, const float* __restrict__ dbh0,
    const float* __restrict__ dW1, const float* __restrict__ dU1,
    const float* __restrict__ dbi1, const float* __restrict__ dbh1,
    const float* __restrict__ oW)
{
    int idx = blockIdx.x * blockDim.x + threadIdx.x;   // 0..65535
    int k = idx >> 9;          // 0..127  (input dim)
    int j = idx & 511;         // 0..511  (gate column)
    int src = j * 128 + k;     // original [4H, H] row-major
    g_E0[idx] = __floats2half2_rn(eW0[src], eU0[src]);
    g_E1[idx] = __floats2half2_rn(eW1[src], eU1[src]);
    g_D0[idx] = __floats2half2_rn(dW0[src], dU0[src]);
    g_D1[idx] = __floats2half2_rn(dW1[src], dU1[src]);
    if (idx < 128 * 128) {
        int kk = idx >> 7, d = idx & 127;
        g_OW[kk * 128 + d] = oW[d * 128 + kk];         // transpose out_W
    }
    if (idx < 512) {
        g_bE0[idx] = ebi0[idx] + ebh0[idx];
        g_bE1[idx] = ebi1[idx] + ebh1[idx];
        g_bD0[idx] = dbi0[idx] + dbh0[idx];
        g_bD1[idx] = dbi1[idx] + dbh1[idx];
    }
}

__device__ __forceinline__ float sigf(float x) {
    return 1.0f / (1.0f + __expf(-x));
}
__device__ __forceinline__ float tanhfa(float x) {
    return 1.0f - 2.0f / (__expf(2.0f * x) + 1.0f);
}

// One LSTM cell step for 4 batch rows.
// gates[b, j] = bias[j] + sum_k ( Wih[j,k]*src[b,k] + Whh[j,k]*h[b,k] )
// Thread j (0..511) computes column j for all 4 rows; then thread (bb,nn)
// applies activations and updates h,c.
__device__ __forceinline__ void lstm_layer(
    const __half2* __restrict__ Wp,    // [128][512] packed (Wih, Whh)
    const float*  __restrict__ bias,   // [512] fused bias
    const float* src,                  // [4][128] shared: layer input
    float* hst, float* cst,            // [4][128] shared: recurrent state
    float* gts,                        // [4][512] shared scratch
    int j, int bb, int nn)
{
    float a0, a1, a2, a3;
    a0 = a1 = a2 = a3 = bias[j];
    const float4* s0 = (const float4*)(src);
    const float4* s1 = (const float4*)(src + 128);
    const float4* s2 = (const float4*)(src + 256);
    const float4* s3 = (const float4*)(src + 384);
    const float4* r0 = (const float4*)(hst);
    const float4* r1 = (const float4*)(hst + 128);
    const float4* r2 = (const float4*)(hst + 256);
    const float4* r3 = (const float4*)(hst + 384);
    const __half2* wp = Wp + j;

#pragma unroll 8
    for (int kk = 0; kk < 32; kk++) {
        float4 xv0 = s0[kk], xv1 = s1[kk], xv2 = s2[kk], xv3 = s3[kk];
        float4 hv0 = r0[kk], hv1 = r1[kk], hv2 = r2[kk], hv3 = r3[kk];
#pragma unroll
        for (int u = 0; u < 4; u++) {
            float2 w = __half22float2(wp[(kk * 4 + u) * 512]);
            a0 = fmaf(w.x, ((const float*)&xv0)[u], a0);
            a0 = fmaf(w.y, ((const float*)&hv0)[u], a0);
            a1 = fmaf(w.x, ((const float*)&xv1)[u], a1);
            a1 = fmaf(w.y, ((const float*)&hv1)[u], a1);
            a2 = fmaf(w.x, ((const float*)&xv2)[u], a2);
            a2 = fmaf(w.y, ((const float*)&hv2)[u], a2);
            a3 = fmaf(w.x, ((const float*)&xv3)[u], a3);
            a3 = fmaf(w.y, ((const float*)&hv3)[u], a3);
        }
    }
    gts[j] = a0; gts[512 + j] = a1; gts[1024 + j] = a2; gts[1536 + j] = a3;
    __syncthreads();

    // activation + state update: thread -> (row bb, hidden unit nn)
    float gi = gts[bb * 512 + nn];
    float gf = gts[bb * 512 + nn + 128];
    float gg = gts[bb * 512 + nn + 256];
    float go = gts[bb * 512 + nn + 384];
    float cn = sigf(gf) * cst[bb * 128 + nn] + sigf(gi) * tanhfa(gg);
    float hn = sigf(go) * tanhfa(cn);
    cst[bb * 128 + nn] = cn;
    hst[bb * 128 + nn] = hn;
    __syncthreads();
}

__global__ void __launch_bounds__(512, 1) lstm_main(
    const float* __restrict__ x, const float* __restrict__ out_b,
    float* __restrict__ out)
{
    __shared__ __align__(16) float s_x [4 * 128];
    __shared__ __align__(16) float s_h0[4 * 128];
    __shared__ __align__(16) float s_c0[4 * 128];
    __shared__ __align__(16) float s_h1[4 * 128];
    __shared__ __align__(16) float s_c1[4 * 128];
    __shared__ __align__(16) float s_g [4 * 512];

    const int j  = threadIdx.x;        // gate column
    const int bb = j >> 7;             // local batch row 0..3
    const int nn = j & 127;            // hidden unit
    const int bg = blockIdx.x * 4;     // global batch base

    s_h0[bb * 128 + nn] = 0.f; s_c0[bb * 128 + nn] = 0.f;
    s_h1[bb * 128 + nn] = 0.f; s_c1[bb * 128 + nn] = 0.f;
    __syncthreads();

    // ---------------- Encoder: 2 stacked layers over T steps ----------------
    const float* xbase = x + (size_t)(bg + bb) * (Tt * Dd) + nn;
    for (int t = 0; t < Tt; t++) {
        s_x[bb * 128 + nn] = xbase[t * Dd];
        __syncthreads();
        lstm_layer(g_E0, g_bE0, s_x,  s_h0, s_c0, s_g, j, bb, nn);
        lstm_layer(g_E1, g_bE1, s_h0, s_h1, s_c1, s_g, j, bb, nn);
    }

    // x0 = encoder layer-1 h at last step; reset all decoder states to zero.
    float x0v = s_h1[bb * 128 + nn];
    __syncthreads();
    s_x [bb * 128 + nn] = x0v;
    s_h0[bb * 128 + nn] = 0.f; s_c0[bb * 128 + nn] = 0.f;
    s_h1[bb * 128 + nn] = 0.f; s_c1[bb * 128 + nn] = 0.f;
    __syncthreads();

    // ---------------- Decoder: 2 layers + projection, h1 fed back ----------
    float* obase = out + (size_t)(bg + bb) * (Tt * Dd) + nn;
    const float ob = out_b[nn];
    for (int t = 0; t < Tt; t++) {
        lstm_layer(g_D0, g_bD0, s_x,  s_h0, s_c0, s_g, j, bb, nn);
        lstm_layer(g_D1, g_bD1, s_h0, s_h1, s_c1, s_g, j, bb, nn);

        // out[b, t, nn] = h1[b,:] . out_W[nn,:] + out_b[nn]
        float acc = ob;
        const float4* hv = (const float4*)(s_h1 + bb * 128);
#pragma unroll 8
        for (int kk = 0; kk < 32; kk++) {
            float4 h4 = hv[kk];
            acc = fmaf(((const float*)&h4)[0], g_OW[(kk * 4 + 0) * 128 + nn], acc);
            acc = fmaf(((const float*)&h4)[1], g_OW[(kk * 4 + 1) * 128 + nn], acc);
            acc = fmaf(((const float*)&h4)[2], g_OW[(kk * 4 + 2) * 128 + nn], acc);
            acc = fmaf(((const float*)&h4)[3], g_OW[(kk * 4 + 3) * 128 + nn], acc);
        }
        obase[t * Dd] = acc;

        // feedback: next step's layer-0 input is h1 (new)
        s_x[bb * 128 + nn] = s_h1[bb * 128 + nn];
        __syncthreads();
    }
}

extern "C" void kernel_launch(void* const* d_in, const int* in_sizes, int n_in,
                              void* d_out, int out_size)
{
    const float* x    = (const float*)d_in[0];
    const float* eW0  = (const float*)d_in[1];
    const float* eU0  = (const float*)d_in[2];
    const float* ebi0 = (const float*)d_in[3];
    const float* ebh0 = (const float*)d_in[4];
    const float* eW1  = (const float*)d_in[5];
    const float* eU1  = (const float*)d_in[6];
    const float* ebi1 = (const float*)d_in[7];
    const float* ebh1 = (const float*)d_in[8];
    const float* dW0  = (const float*)d_in[9];
    const float* dU0  = (const float*)d_in[10];
    const float* dbi0 = (const float*)d_in[11];
    const float* dbh0 = (const float*)d_in[12];
    const float* dW1  = (const float*)d_in[13];
    const float* dU1  = (const float*)d_in[14];
    const float* dbi1 = (const float*)d_in[15];
    const float* dbh1 = (const float*)d_in[16];
    const float* oW   = (const float*)d_in[17];
    const float* ob   = (const float*)d_in[18];
    float* out = (float*)d_out;

    prep_kernel<<<128, 512>>>(eW0, eU0, ebi0, ebh0,
                              eW1, eU1, ebi1, ebh1,
                              dW0, dU0, dbi0, dbh0,
                              dW1, dU1, dbi1, dbh1, oW);
    lstm_main<<<128, 512>>>(x, ob, out);
}

// round 2
// speedup vs baseline: 1.0001x; 1.0001x over previous
#include <cuda_runtime.h>
#include <cuda_fp16.h>

// LSTM Autoencoder: B=512, T=256, D=H=128, gates G=4H=512.
// Persistent kernel: 128 CTAs x 512 threads; each CTA owns 4 batch rows and the
// full recurrence (encoder 2 layers -> decoder 2 layers + output projection).
// Batch rows are independent => no cross-CTA sync.
// Weights pre-packed by prep_kernel into k-major __half2 (Wih,Whh) pairs to
// halve L2 traffic; all state/accumulation in fp32.

#define Bsz 512
#define Tt  256
#define Dd  128
#define Hh  128
#define Gg  512

// __device__ scratch (allocation-free rule): packed weights + fused biases.
__device__ __align__(16) __half2 g_E0[128 * 512];
__device__ __align__(16) __half2 g_E1[128 * 512];
__device__ __align__(16) __half2 g_D0[128 * 512];
__device__ __align__(16) __half2 g_D1[128 * 512];
__device__ __align__(16) float   g_OW[128 * 128];   // out_W transposed: [k][d]
__device__ float g_bE0[512], g_bE1[512], g_bD0[512], g_bD1[512];

__global__ void prep_kernel(
    const float* __restrict__ eW0, const float* __restrict__ eU0,
    const float* __restrict__ ebi0, const float* __restrict__ ebh0,
    const float* __restrict__ eW1, const float* __restrict__ eU1,
    const float* __restrict__ ebi1, const float* __restrict__ ebh1,
    const float* __restrict__ dW0, const float* __restrict__ dU0,
    const float* __restrict__ dbi0, const float* __restrict__ dbh0,
    const float* __restrict__ dW1, const float* __restrict__ dU1,
    const float* __restrict__ dbi1, const float* __restrict__ dbh1,
    const float* __restrict__ oW)
{
    int idx = blockIdx.x * blockDim.x + threadIdx.x;   // 0..65535
    int k = idx >> 9;          // 0..127  (input dim)
    int j = idx & 511;         // 0..511  (gate column)
    int src = j * 128 + k;     // original [4H, H] row-major
    g_E0[idx] = __floats2half2_rn(eW0[src], eU0[src]);
    g_E1[idx] = __floats2half2_rn(eW1[src], eU1[src]);
    g_D0[idx] = __floats2half2_rn(dW0[src], dU0[src]);
    g_D1[idx] = __floats2half2_rn(dW1[src], dU1[src]);
    if (idx < 128 * 128) {
        int kk = idx >> 7, d = idx & 127;
        g_OW[kk * 128 + d] = oW[d * 128 + kk];         // transpose out_W
    }
    if (idx < 512) {
        g_bE0[idx] = ebi0[idx] + ebh0[idx];
        g_bE1[idx] = ebi1[idx] + ebh1[idx];
        g_bD0[idx] = dbi0[idx] + dbh0[idx];
        g_bD1[idx] = dbi1[idx] + dbh1[idx];
    }
}

__device__ __forceinline__ float sigf(float x) {
    return 1.0f / (1.0f + __expf(-x));
}
__device__ __forceinline__ float tanhfa(float x) {
    return 1.0f - 2.0f / (__expf(2.0f * x) + 1.0f);
}

// One LSTM cell step for 4 batch rows.
// gates[b, j] = bias[j] + sum_k ( Wih[j,k]*src[b,k] + Whh[j,k]*h[b,k] )
// Thread j (0..511) computes column j for all 4 rows; then thread (bb,nn)
// applies activations and updates h,c.
__device__ __forceinline__ void lstm_layer(
    const __half2* __restrict__ Wp,    // [128][512] packed (Wih, Whh)
    const float*  __restrict__ bias,   // [512] fused bias
    const float* src,                  // [4][128] shared: layer input
    float* hst, float* cst,            // [4][128] shared: recurrent state
    float* gts,                        // [4][512] shared scratch
    int j, int bb, int nn)
{
    float a0, a1, a2, a3;
    a0 = a1 = a2 = a3 = bias[j];
    const float4* s0 = (const float4*)(src);
    const float4* s1 = (const float4*)(src + 128);
    const float4* s2 = (const float4*)(src + 256);
    const float4* s3 = (const float4*)(src + 384);
    const float4* r0 = (const float4*)(hst);
    const float4* r1 = (const float4*)(hst + 128);
    const float4* r2 = (const float4*)(hst + 256);
    const float4* r3 = (const float4*)(hst + 384);
    const __half2* wp = Wp + j;

#pragma unroll 8
    for (int kk = 0; kk < 32; kk++) {
        float4 xv0 = s0[kk], xv1 = s1[kk], xv2 = s2[kk], xv3 = s3[kk];
        float4 hv0 = r0[kk], hv1 = r1[kk], hv2 = r2[kk], hv3 = r3[kk];
#pragma unroll
        for (int u = 0; u < 4; u++) {
            float2 w = __half22float2(wp[(kk * 4 + u) * 512]);
            a0 = fmaf(w.x, ((const float*)&xv0)[u], a0);
            a0 = fmaf(w.y, ((const float*)&hv0)[u], a0);
            a1 = fmaf(w.x, ((const float*)&xv1)[u], a1);
            a1 = fmaf(w.y, ((const float*)&hv1)[u], a1);
            a2 = fmaf(w.x, ((const float*)&xv2)[u], a2);
            a2 = fmaf(w.y, ((const float*)&hv2)[u], a2);
            a3 = fmaf(w.x, ((const float*)&xv3)[u], a3);
            a3 = fmaf(w.y, ((const float*)&hv3)[u], a3);
        }
    }
    gts[j] = a0; gts[512 + j] = a1; gts[1024 + j] = a2; gts[1536 + j] = a3;
    __syncthreads();

    // activation + state update: thread -> (row bb, hidden unit nn)
    float gi = gts[bb * 512 + nn];
    float gf = gts[bb * 512 + nn + 128];
    float gg = gts[bb * 512 + nn + 256];
    float go = gts[bb * 512 + nn + 384];
    float cn = sigf(gf) * cst[bb * 128 + nn] + sigf(gi) * tanhfa(gg);
    float hn = sigf(go) * tanhfa(cn);
    cst[bb * 128 + nn] = cn;
    hst[bb * 128 + nn] = hn;
    __syncthreads();
}

__global__ void __launch_bounds__(512, 1) lstm_main(
    const float* __restrict__ x, const float* __restrict__ out_b,
    float* __restrict__ out)
{
    __shared__ __align__(16) float s_x [4 * 128];
    __shared__ __align__(16) float s_h0[4 * 128];
    __shared__ __align__(16) float s_c0[4 * 128];
    __shared__ __align__(16) float s_h1[4 * 128];
    __shared__ __align__(16) float s_c1[4 * 128];
    __shared__ __align__(16) float s_g [4 * 512];

    const int j  = threadIdx.x;        // gate column
    const int bb = j >> 7;             // local batch row 0..3
    const int nn = j & 127;            // hidden unit
    const int bg = blockIdx.x * 4;     // global batch base

    s_h0[bb * 128 + nn] = 0.f; s_c0[bb * 128 + nn] = 0.f;
    s_h1[bb * 128 + nn] = 0.f; s_c1[bb * 128 + nn] = 0.f;
    __syncthreads();

    // ---------------- Encoder: 2 stacked layers over T steps ----------------
    const float* xbase = x + (size_t)(bg + bb) * (Tt * Dd) + nn;
    for (int t = 0; t < Tt; t++) {
        s_x[bb * 128 + nn] = xbase[t * Dd];
        __syncthreads();
        lstm_layer(g_E0, g_bE0, s_x,  s_h0, s_c0, s_g, j, bb, nn);
        lstm_layer(g_E1, g_bE1, s_h0, s_h1, s_c1, s_g, j, bb, nn);
    }

    // x0 = encoder layer-1 h at last step; reset all decoder states to zero.
    float x0v = s_h1[bb * 128 + nn];
    __syncthreads();
    s_x [bb * 128 + nn] = x0v;
    s_h0[bb * 128 + nn] = 0.f; s_c0[bb * 128 + nn] = 0.f;
    s_h1[bb * 128 + nn] = 0.f; s_c1[bb * 128 + nn] = 0.f;
    __syncthreads();

    // ---------------- Decoder: 2 layers + projection, h1 fed back ----------
    float* obase = out + (size_t)(bg + bb) * (Tt * Dd) + nn;
    const float ob = out_b[nn];
    for (int t = 0; t < Tt; t++) {
        lstm_layer(g_D0, g_bD0, s_x,  s_h0, s_c0, s_g, j, bb, nn);
        lstm_layer(g_D1, g_bD1, s_h0, s_h1, s_c1, s_g, j, bb, nn);

        // out[b, t, nn] = h1[b,:] . out_W[nn,:] + out_b[nn]
        float acc = ob;
        const float4* hv = (const float4*)(s_h1 + bb * 128);
#pragma unroll 8
        for (int kk = 0; kk < 32; kk++) {
            float4 h4 = hv[kk];
            acc = fmaf(((const float*)&h4)[0], g_OW[(kk * 4 + 0) * 128 + nn], acc);
            acc = fmaf(((const float*)&h4)[1], g_OW[(kk * 4 + 1) * 128 + nn], acc);
            acc = fmaf(((const float*)&h4)[2], g_OW[(kk * 4 + 2) * 128 + nn], acc);
            acc = fmaf(((const float*)&h4)[3], g_OW[(kk * 4 + 3) * 128 + nn], acc);
        }
        obase[t * Dd] = acc;

        // feedback: next step's layer-0 input is h1 (new)
        s_x[bb * 128 + nn] = s_h1[bb * 128 + nn];
        __syncthreads();
    }
}

extern "C" void kernel_launch(void* const* d_in, const int* in_sizes, int n_in,
                              void* d_out, int out_size)
{
    const float* x    = (const float*)d_in[0];
    const float* eW0  = (const float*)d_in[1];
    const float* eU0  = (const float*)d_in[2];
    const float* ebi0 = (const float*)d_in[3];
    const float* ebh0 = (const float*)d_in[4];
    const float* eW1  = (const float*)d_in[5];
    const float* eU1  = (const float*)d_in[6];
    const float* ebi1 = (const float*)d_in[7];
    const float* ebh1 = (const float*)d_in[8];
    const float* dW0  = (const float*)d_in[9];
    const float* dU0  = (const float*)d_in[10];
    const float* dbi0 = (const float*)d_in[11];
    const float* dbh0 = (const float*)d_in[12];
    const float* dW1  = (const float*)d_in[13];
    const float* dU1  = (const float*)d_in[14];
    const float* dbi1 = (const float*)d_in[15];
    const float* dbh1 = (const float*)d_in[16];
    const float* oW   = (const float*)d_in[17];
    const float* ob   = (const float*)d_in[18];
    float* out = (float*)d_out;

    prep_kernel<<<128, 512>>>(eW0, eU0, ebi0, ebh0,
                              eW1, eU1, ebi1, ebh1,
                              dW0, dU0, dbi0, dbh0,
                              dW1, dU1, dbi1, dbh1, oW);
    lstm_main<<<128, 512>>>(x, ob, out);
}